// round 12
// baseline (speedup 1.0000x reference)
#include <cuda_runtime.h>
#include <math.h>
#include <stdint.h>

// Problem constants
#define N_ROWS 2048
#define D_DIM  192
#define C_CLS  100000
#define S_SCALE 30.0f
#define MARGIN  0.2f

#define NT256 391         // class tiles of 256 (391*256 = 100096)
#define CPAD  100096
#define STRIPES 37        // grid (37,16) = 592 CTAs = 4 waves @ 1 CTA/SM
#define NPART (STRIPES * 8)   // 296 partials per row
#define B_CLS 256

// smem layout (bytes)
#define A_BYTES  49152                        // 96 frags x 32 lanes x 16B
#define B_CSTR   26                           // uint2 per class row (24 data + 2 pad)
#define B_BUFU2  (32 * B_CSTR)                // 832 uint2 per stage
#define B_BYTES  (8 * 3 * B_BUFU2 * 8)        // 159744
#define SMEM_TOTAL (A_BYTES + B_BYTES)        // 208896

// ---------------- scratch globals ----------------
__device__ __align__(16) float g_xn[N_ROWS * D_DIM];
__device__ __align__(16) unsigned short g_wbf[(size_t)CPAD * D_DIM];  // bf16, k-pair permuted
__device__ float g_tgt[N_ROWS];
__device__ float g_psum[(size_t)N_ROWS * NPART];
__device__ float g_L[N_ROWS];
__device__ int   g_lab32;

// ---------------- helpers (sm_80-level PTX only) ----------------
__device__ __forceinline__ uint32_t smem_u32(const void* p) {
    uint32_t a;
    asm("{ .reg .u64 t; cvta.to.shared.u64 t, %1; cvt.u32.u64 %0, t; }" : "=r"(a) : "l"(p));
    return a;
}
__device__ __forceinline__ void cp16(uint32_t dst, const void* src) {
    asm volatile("cp.async.cg.shared.global [%0], [%1], 16;" :: "r"(dst), "l"(src) : "memory");
}
#define CP_COMMIT() asm volatile("cp.async.commit_group;" ::: "memory")
#define CP_WAIT(n)  asm volatile("cp.async.wait_group %0;" :: "n"(n) : "memory")
#define PAIR_BAR(id) asm volatile("bar.sync %0, 64;" :: "r"(id) : "memory")

// pack(lo, hi): bf16x2 register {hi:lo}
__device__ __forceinline__ uint32_t bfpack(float lo, float hi) {
    uint32_t r;
    asm("cvt.rn.bf16x2.f32 %0, %1, %2;" : "=r"(r) : "f"(hi), "f"(lo));
    return r;
}

__device__ __forceinline__ void mma16(float* c, const uint32_t* a, uint32_t b0, uint32_t b1) {
    asm volatile(
        "mma.sync.aligned.m16n8k16.row.col.f32.bf16.bf16.f32 "
        "{%0,%1,%2,%3}, {%4,%5,%6,%7}, {%8,%9}, {%0,%1,%2,%3};"
        : "+f"(c[0]), "+f"(c[1]), "+f"(c[2]), "+f"(c[3])
        : "r"(a[0]), "r"(a[1]), "r"(a[2]), "r"(a[3]), "r"(b0), "r"(b1));
}

// exp(S*d) = 2^(S*log2(e)*d) via MUFU ex2
__device__ __forceinline__ float exp_s(float d) {
    float r;
    asm("ex2.approx.f32 %0, %1;" : "=f"(r) : "f"(43.2808512266689f * d));
    return r;
}

// ---------------------------------------------------------------------------
// Kernel 0: label dtype detect (touches only first 8KB; safe either way)
// ---------------------------------------------------------------------------
__global__ void detect_label_kernel(const int* __restrict__ lab) {
    __shared__ int any;
    if (threadIdx.x == 0) any = 0;
    __syncthreads();
    int v = 0;
    for (int i = threadIdx.x; i < 1024; i += blockDim.x) v |= lab[2 * i + 1];
    if (v) atomicOr(&any, 1);
    __syncthreads();
    if (threadIdx.x == 0) g_lab32 = (any != 0) ? 1 : 0;
}

// ---------------------------------------------------------------------------
// Kernel 0b: W (f32) -> g_wbf (bf16), permuted per k16 block so a B fragment
// (k pairs {2qt,2qt+1} and {2qt+8,2qt+9}) is one aligned 8-byte word pair.
// Word order per k16: (0,1)(8,9)(2,3)(10,11)(4,5)(12,13)(6,7)(14,15).
// ---------------------------------------------------------------------------
__global__ void convertW_kernel(const float* __restrict__ W) {
    int idx = blockIdx.x * blockDim.x + threadIdx.x;   // (cls, ks) pair
    if (idx >= CPAD * 12) return;
    int cls = idx / 12, ks = idx % 12;
    int cr = cls < C_CLS ? cls : C_CLS - 1;
    const float* wr = W + (size_t)cr * D_DIM + ks * 16;
    float v[16];
#pragma unroll
    for (int j = 0; j < 4; j++) {
        float4 t = ((const float4*)wr)[j];
        v[4 * j] = t.x; v[4 * j + 1] = t.y; v[4 * j + 2] = t.z; v[4 * j + 3] = t.w;
    }
    const int ps[8] = {0, 8, 2, 10, 4, 12, 6, 14};
    uint32_t o[8];
#pragma unroll
    for (int j = 0; j < 8; j++) o[j] = bfpack(v[ps[j]], v[ps[j] + 1]);
    uint4* dst = (uint4*)(g_wbf + (size_t)cls * D_DIM + ks * 16);
    dst[0] = make_uint4(o[0], o[1], o[2], o[3]);
    dst[1] = make_uint4(o[4], o[5], o[6], o[7]);
}

// ---------------------------------------------------------------------------
// Kernel 1: row normalize + exact target logit (fp32)
// ---------------------------------------------------------------------------
__global__ void norm_tgt_kernel(const float* __restrict__ x,
                                const float* __restrict__ W,
                                const void* __restrict__ label) {
    int warp = (blockIdx.x * blockDim.x + threadIdx.x) >> 5;
    int lane = threadIdx.x & 31;
    if (warp >= N_ROWS) return;

    const float* xr = x + (size_t)warp * D_DIM;
    float xv[6], ss = 0.f;
#pragma unroll
    for (int j = 0; j < 6; j++) { xv[j] = xr[lane + 32 * j]; ss += xv[j] * xv[j]; }
#pragma unroll
    for (int o = 16; o; o >>= 1) ss += __shfl_xor_sync(0xffffffffu, ss, o);
    float inv = rsqrtf(ss);

    long long li = g_lab32 ? (long long)((const int*)label)[warp]
                           : ((const long long*)label)[warp];
    if (li < 0) li = 0;
    if (li >= C_CLS) li = C_CLS - 1;

    const float* wr = W + (size_t)li * D_DIM;
    float dot = 0.f;
#pragma unroll
    for (int j = 0; j < 6; j++) {
        g_xn[(size_t)warp * D_DIM + lane + 32 * j] = xv[j] * inv;
        dot += xv[j] * wr[lane + 32 * j];
    }
#pragma unroll
    for (int o = 16; o; o >>= 1) dot += __shfl_xor_sync(0xffffffffu, dot, o);
    if (lane == 0) g_tgt[warp] = dot * inv;
}

// ---------------------------------------------------------------------------
// Kernel 2: bf16 mma.sync m16n8k16 GEMM, 128 rows x 256 classes per CTA tile.
// NO block barriers in the main loop: each wn warp-pair (wm=0,1) owns a
// private 3-stage B ring in smem filled by pair-cooperative cp.async and
// synchronized with a named 64-thread barrier (bar.sync 1+wn). A is shared
// read-only smem (one __syncthreads after the prologue). 96-k chunks.
//   warp grid 2(m) x 8(n); warp tile 64x32; 4(mt) x 4(nt) fragments.
// ---------------------------------------------------------------------------
__global__ void __launch_bounds__(512, 1) gemm_lse_mma() {
    extern __shared__ uint32_t smw[];
    uint4* As4 = (uint4*)smw;                         // [96 frags][32 lanes]
    uint2* Ball = (uint2*)((char*)smw + A_BYTES);     // 8 wn x 3 stages x 832

    const int tid  = threadIdx.x;
    const int wid  = tid >> 5;
    const int lane = tid & 31;
    const int wm = wid >> 3, wn = wid & 7;
    const int qid = lane >> 2, qt = lane & 3;
    const int rowBase = blockIdx.y * 128;
    const int ct0 = blockIdx.x;
    const int barid = 1 + wn;

    // ---- stage A once as bf16 m16n8k16 fragments ----
    for (int f = wid; f < 96; f += 16) {
        int fm = f / 12, ks = f % 12;
        const float* b0 = g_xn + (size_t)(rowBase + fm * 16 + qid) * D_DIM + ks * 16 + 2 * qt;
        const float* b8 = b0 + 8 * D_DIM;
        As4[f * 32 + lane] = make_uint4(
            bfpack(b0[0], b0[1]), bfpack(b8[0], b8[1]),
            bfpack(b0[8], b0[9]), bfpack(b8[8], b8[9]));
    }
    __syncthreads();     // the only block-wide barrier

    uint2* Bpair = Ball + wn * 3 * B_BUFU2;           // this pair's 3-stage ring
    const uint2* __restrict__ gw2 = (const uint2*)g_wbf;   // 48 uint2 per class

    // pair-cooperative chunk load: chunk c (96k = 12 uint2-pairs/class) of tile
    // ct into stage buf. 64 threads x 6 cp16 = 384 cp16 = 32 cls x 12.
    const int p = wm * 32 + lane;                     // 0..63 within pair
    auto loadB = [&](int ct, int c, int buf) {
        uint2* bs = Bpair + buf * B_BUFU2;
        int clsBase = ct * B_CLS + wn * 32;
        int cl0 = p & 31, j0 = (p >> 5) * 6;          // lane -> class, 6 j-slots
#pragma unroll
        for (int i = 0; i < 6; i++) {
            int j = j0 + i;                           // 0..11 (16B unit)
            cp16(smem_u32(bs + cl0 * B_CSTR + 2 * j),
                 gw2 + (size_t)(clsBase + cl0) * 48 + c * 24 + 2 * j);
        }
        CP_COMMIT();
    };

    const int ntiles = (NT256 - 1 - ct0) / STRIPES + 1;
    const int total  = ntiles * 2;

    loadB(ct0, 0, 0);
    if (total > 1) loadB(ct0, 1, 1);

    float rsum[4][2] = {};
    float acc[4][4][4];
    const uint4* af0 = As4 + (wm * 4) * 12 * 32 + lane;

    for (int g = 0; g < total; ++g) {
        const int c  = g & 1;
        const int ct = ct0 + (g >> 1) * STRIPES;

        if (g == total - 1) { CP_WAIT(0); } else { CP_WAIT(1); }
        PAIR_BAR(barid);   // pair done reading buf (g-1)%3; chunk g visible

        if (g + 2 < total) {
            int gn = g + 2;
            loadB(ct0 + (gn >> 1) * STRIPES, gn & 1, gn % 3);
        }

        if (c == 0) {
#pragma unroll
            for (int mt = 0; mt < 4; mt++)
#pragma unroll
                for (int nt = 0; nt < 4; nt++)
#pragma unroll
                    for (int e = 0; e < 4; e++) acc[mt][nt][e] = 0.f;
        }

        const uint2* bs = Bpair + (g % 3) * B_BUFU2;
        const uint4* af = af0 + c * 6 * 32;
        const uint2* bb = bs + qid * B_CSTR + qt;     // + nt*8*B_CSTR + ks*4
#pragma unroll
        for (int ks = 0; ks < 6; ks++) {
            uint4 a[4];
#pragma unroll
            for (int mt = 0; mt < 4; mt++)
                a[mt] = af[(mt * 12 + ks) * 32];
#pragma unroll
            for (int nt = 0; nt < 4; nt++) {
                const uint2 b = bb[nt * 8 * B_CSTR + ks * 4];
#pragma unroll
                for (int mt = 0; mt < 4; mt++)
                    mma16(acc[mt][nt], (const uint32_t*)&a[mt], b.x, b.y);
            }
        }

        if (c == 1) {
            if (ct != NT256 - 1) {
#pragma unroll
                for (int mt = 0; mt < 4; mt++)
#pragma unroll
                    for (int nt = 0; nt < 4; nt++) {
                        rsum[mt][0] += exp_s(acc[mt][nt][0]) + exp_s(acc[mt][nt][1]);
                        rsum[mt][1] += exp_s(acc[mt][nt][2]) + exp_s(acc[mt][nt][3]);
                    }
            } else {
#pragma unroll
                for (int mt = 0; mt < 4; mt++)
#pragma unroll
                    for (int nt = 0; nt < 4; nt++) {
                        int cls0 = ct * B_CLS + wn * 32 + nt * 8 + 2 * qt;
                        if (cls0 < C_CLS)     { rsum[mt][0] += exp_s(acc[mt][nt][0]);
                                                rsum[mt][1] += exp_s(acc[mt][nt][2]); }
                        if (cls0 + 1 < C_CLS) { rsum[mt][0] += exp_s(acc[mt][nt][1]);
                                                rsum[mt][1] += exp_s(acc[mt][nt][3]); }
                    }
            }
        }
    }

    // ---- one partial per (stripe, wn) per row ----
    const int cidx = blockIdx.x * 8 + wn;
#pragma unroll
    for (int mt = 0; mt < 4; mt++) {
        float sLo = rsum[mt][0], sHi = rsum[mt][1];
        sLo += __shfl_xor_sync(0xffffffffu, sLo, 1);
        sLo += __shfl_xor_sync(0xffffffffu, sLo, 2);
        sHi += __shfl_xor_sync(0xffffffffu, sHi, 1);
        sHi += __shfl_xor_sync(0xffffffffu, sHi, 2);
        if (qt == 0) {
            int row = rowBase + wm * 64 + mt * 16 + qid;
            g_psum[(size_t)row * NPART + cidx]       = sLo;
            g_psum[(size_t)(row + 8) * NPART + cidx] = sHi;
        }
    }
}

// ---------------------------------------------------------------------------
// Kernel 3: warp per row: sum 296 partials + margin correction
// ---------------------------------------------------------------------------
__global__ void combine_kernel() {
    int row  = blockIdx.x * 8 + (threadIdx.x >> 5);
    int lane = threadIdx.x & 31;
    const float* p = g_psum + (size_t)row * NPART;
    float s = 0.f;
    for (int c = lane; c < NPART; c += 32) s += p[c];
#pragma unroll
    for (int o = 16; o; o >>= 1) s += __shfl_xor_sync(0xffffffffu, s, o);
    if (lane == 0) {
        float tgt   = g_tgt[row];
        float numer = S_SCALE * (tgt - MARGIN);
        float scorr = s - expf(S_SCALE * tgt) + expf(numer);
        g_L[row] = numer - logf(scorr);
    }
}

// ---------------------------------------------------------------------------
// Kernel 4: mean
// ---------------------------------------------------------------------------
__global__ void final_kernel(float* __restrict__ out) {
    __shared__ float sm[1024];
    int t = threadIdx.x;
    sm[t] = g_L[t] + g_L[t + 1024];
    __syncthreads();
    for (int st = 512; st > 0; st >>= 1) {
        if (t < st) sm[t] += sm[t + st];
        __syncthreads();
    }
    if (t == 0) out[0] = -sm[0] / (float)N_ROWS;
}

// ---------------------------------------------------------------------------
extern "C" void kernel_launch(void* const* d_in, const int* in_sizes, int n_in,
                              void* d_out, int out_size) {
    (void)in_sizes; (void)n_in; (void)out_size;
    const float* x     = (const float*)d_in[0];
    const float* W     = (const float*)d_in[1];
    const void*  label = d_in[2];
    float* out = (float*)d_out;

    cudaFuncSetAttribute(gemm_lse_mma, cudaFuncAttributeMaxDynamicSharedMemorySize, SMEM_TOTAL);

    detect_label_kernel<<<1, 256>>>((const int*)label);
    convertW_kernel<<<(CPAD * 12 + 255) / 256, 256>>>(W);
    norm_tgt_kernel<<<N_ROWS / 8, 256>>>(x, W, label);

    dim3 grid(STRIPES, N_ROWS / 128);
    gemm_lse_mma<<<grid, 512, SMEM_TOTAL>>>();

    combine_kernel<<<N_ROWS / 8, 256>>>();
    final_kernel<<<1, 1024>>>(out);
}

// round 13
// speedup vs baseline: 1.3389x; 1.3389x over previous
#include <cuda_runtime.h>
#include <math.h>
#include <stdint.h>

// Problem constants
#define N_ROWS 2048
#define D_DIM  192
#define C_CLS  100000
#define S_SCALE 30.0f
#define MARGIN  0.2f

#define NT256 391         // class tiles of 256 (391*256 = 100096)
#define CPAD  100096
#define NGRP  (CPAD / 8)  // 12512 class-groups of 8
#define STRIPES 37        // grid (37,16) = 592 CTAs = 4 waves @ 1 CTA/SM (512 thr)
#define NPART (STRIPES * 8)   // 296 partials per row
#define B_CLS 256

// ---------------- scratch globals ----------------
__device__ __align__(16) float g_xn[N_ROWS * D_DIM];
// B in warp-fragment-contiguous layout:
//   uint2 index = ((grp8 * 12 + ks) * 8 + (cls & 7)) * 4 + qt
// so a warp's (nt, ks) fragment = 32 consecutive uint2 (256 B, one LDG.64/warp).
__device__ __align__(16) uint2 g_wb2[(size_t)NGRP * 12 * 32];
__device__ float g_tgt[N_ROWS];
__device__ float g_psum[(size_t)N_ROWS * NPART];
__device__ float g_L[N_ROWS];
__device__ int   g_lab32;

// ---------------- helpers (sm_80-level PTX only) ----------------
// pack(lo, hi): bf16x2 register {hi:lo}
__device__ __forceinline__ uint32_t bfpack(float lo, float hi) {
    uint32_t r;
    asm("cvt.rn.bf16x2.f32 %0, %1, %2;" : "=r"(r) : "f"(hi), "f"(lo));
    return r;
}

__device__ __forceinline__ void mma16(float* c, const uint32_t* a, uint32_t b0, uint32_t b1) {
    asm volatile(
        "mma.sync.aligned.m16n8k16.row.col.f32.bf16.bf16.f32 "
        "{%0,%1,%2,%3}, {%4,%5,%6,%7}, {%8,%9}, {%0,%1,%2,%3};"
        : "+f"(c[0]), "+f"(c[1]), "+f"(c[2]), "+f"(c[3])
        : "r"(a[0]), "r"(a[1]), "r"(a[2]), "r"(a[3]), "r"(b0), "r"(b1));
}

// exp(S*d) = 2^(S*log2(e)*d) via MUFU ex2
__device__ __forceinline__ float exp_s(float d) {
    float r;
    asm("ex2.approx.f32 %0, %1;" : "=f"(r) : "f"(43.2808512266689f * d));
    return r;
}

// ---------------------------------------------------------------------------
// Kernel 0: label dtype detect (touches only first 8KB; safe either way)
// ---------------------------------------------------------------------------
__global__ void detect_label_kernel(const int* __restrict__ lab) {
    __shared__ int any;
    if (threadIdx.x == 0) any = 0;
    __syncthreads();
    int v = 0;
    for (int i = threadIdx.x; i < 1024; i += blockDim.x) v |= lab[2 * i + 1];
    if (v) atomicOr(&any, 1);
    __syncthreads();
    if (threadIdx.x == 0) g_lab32 = (any != 0) ? 1 : 0;
}

// ---------------------------------------------------------------------------
// Kernel 0b: W (f32) -> g_wb2 (bf16), fragment-contiguous layout.
// Per (cls, ks): qt word = k-pairs {2qt,2qt+1} and {2qt+8,2qt+9} (uint2).
// Destination: ((cls/8)*12 + ks)*32 + (cls%8)*4 + qt  — the 4 qt words of one
// class are 32B contiguous, written as 2 uint4.
// ---------------------------------------------------------------------------
__global__ void convertW_kernel(const float* __restrict__ W) {
    int idx = blockIdx.x * blockDim.x + threadIdx.x;   // (cls, ks) pair
    if (idx >= CPAD * 12) return;
    int cls = idx / 12, ks = idx % 12;
    int cr = cls < C_CLS ? cls : C_CLS - 1;
    const float* wr = W + (size_t)cr * D_DIM + ks * 16;
    float v[16];
#pragma unroll
    for (int j = 0; j < 4; j++) {
        float4 t = ((const float4*)wr)[j];
        v[4 * j] = t.x; v[4 * j + 1] = t.y; v[4 * j + 2] = t.z; v[4 * j + 3] = t.w;
    }
    const int ps[8] = {0, 8, 2, 10, 4, 12, 6, 14};   // qt-word k-pair order
    uint32_t o[8];
#pragma unroll
    for (int j = 0; j < 8; j++) o[j] = bfpack(v[ps[j]], v[ps[j] + 1]);
    uint4* dst = (uint4*)(g_wb2 + ((size_t)(cls >> 3) * 12 + ks) * 32 + (cls & 7) * 4);
    dst[0] = make_uint4(o[0], o[1], o[2], o[3]);
    dst[1] = make_uint4(o[4], o[5], o[6], o[7]);
}

// ---------------------------------------------------------------------------
// Kernel 1: row normalize + exact target logit (fp32)
// ---------------------------------------------------------------------------
__global__ void norm_tgt_kernel(const float* __restrict__ x,
                                const float* __restrict__ W,
                                const void* __restrict__ label) {
    int warp = (blockIdx.x * blockDim.x + threadIdx.x) >> 5;
    int lane = threadIdx.x & 31;
    if (warp >= N_ROWS) return;

    const float* xr = x + (size_t)warp * D_DIM;
    float xv[6], ss = 0.f;
#pragma unroll
    for (int j = 0; j < 6; j++) { xv[j] = xr[lane + 32 * j]; ss += xv[j] * xv[j]; }
#pragma unroll
    for (int o = 16; o; o >>= 1) ss += __shfl_xor_sync(0xffffffffu, ss, o);
    float inv = rsqrtf(ss);

    long long li = g_lab32 ? (long long)((const int*)label)[warp]
                           : ((const long long*)label)[warp];
    if (li < 0) li = 0;
    if (li >= C_CLS) li = C_CLS - 1;

    const float* wr = W + (size_t)li * D_DIM;
    float dot = 0.f;
#pragma unroll
    for (int j = 0; j < 6; j++) {
        g_xn[(size_t)warp * D_DIM + lane + 32 * j] = xv[j] * inv;
        dot += xv[j] * wr[lane + 32 * j];
    }
#pragma unroll
    for (int o = 16; o; o >>= 1) dot += __shfl_xor_sync(0xffffffffu, dot, o);
    if (lane == 0) g_tgt[warp] = dot * inv;
}

// ---------------------------------------------------------------------------
// Kernel 2: bf16 mma.sync m16n8k16 GEMM, 128 rows x 256 classes per tile.
// B streamed gmem->registers, ONE coalesced 256B LDG.64 per warp fragment
// (fragment-contiguous g_wb2 layout). 3-slot distance-2 prefetch ring.
// NO barriers in the main loop; 512 threads, 16 warps free-running.
//   warp grid 2(m) x 8(n); warp tile 64x32; 4(mt) x 4(nt) fragments.
// ---------------------------------------------------------------------------
__global__ void __launch_bounds__(512, 1) gemm_lse_mma() {
    __shared__ uint4 As4[96 * 32];        // [96 frags][32 lanes] = 48 KB

    const int tid  = threadIdx.x;
    const int wid  = tid >> 5;
    const int lane = tid & 31;
    const int wm = wid >> 3, wn = wid & 7;
    const int qid = lane >> 2, qt = lane & 3;
    const int rowBase = blockIdx.y * 128;
    const int ct0 = blockIdx.x;

    // ---- stage A once as bf16 m16n8k16 fragments ----
    // frag f = fm*12 + ks; fm = 16-row group (0..7), ks = k16 step (0..11)
    for (int f = wid; f < 96; f += 16) {
        int fm = f / 12, ks = f % 12;
        const float* b0 = g_xn + (size_t)(rowBase + fm * 16 + qid) * D_DIM + ks * 16 + 2 * qt;
        const float* b8 = b0 + 8 * D_DIM;
        As4[f * 32 + lane] = make_uint4(
            bfpack(b0[0], b0[1]), bfpack(b8[0], b8[1]),
            bfpack(b0[8], b0[9]), bfpack(b8[8], b8[9]));
    }
    __syncthreads();      // the only block barrier

    const uint2* __restrict__ gw = g_wb2;
    const int ntiles = (NT256 - 1 - ct0) / STRIPES + 1;

    // Coalesced B fragment fetch: warp grp base for nt=0 is ct*32 + wn*4.
    auto fetchB = [&](uint2* dst, int ct, int ks) {
        size_t base = (((size_t)(ct * 32 + wn * 4)) * 12 + ks) * 32 + lane;
#pragma unroll
        for (int nt = 0; nt < 4; nt++)
            dst[nt] = gw[base + (size_t)nt * 12 * 32];   // one 256B LDG.64 each
    };

    uint2 bring[3][4];    // prefetch ring, distance 2
    fetchB(bring[0], ct0, 0);
    fetchB(bring[1], ct0, 1);

    float rsum[4][2] = {};
    float acc[4][4][4];

    const uint4* af0 = As4 + (wm * 4) * 12 * 32 + lane;

    for (int t = 0; t < ntiles; t++) {
        const int ct  = ct0 + t * STRIPES;
        const int ctn = (t + 1 < ntiles) ? ct + STRIPES : ct;

#pragma unroll
        for (int ks = 0; ks < 12; ks++) {
            // prefetch (ks+2) into the slot freed last iteration
            {
                const int kq  = (ks + 2 < 12) ? ks + 2 : ks - 10;
                const int ctp = (ks + 2 < 12) ? ct : ctn;
                fetchB(bring[(ks + 2) % 3], ctp, kq);
            }

            if (ks == 0) {
#pragma unroll
                for (int mt = 0; mt < 4; mt++)
#pragma unroll
                    for (int nt = 0; nt < 4; nt++)
#pragma unroll
                        for (int e = 0; e < 4; e++) acc[mt][nt][e] = 0.f;
            }

            uint4 a[4];
#pragma unroll
            for (int mt = 0; mt < 4; mt++)
                a[mt] = af0[(mt * 12 + ks) * 32];

            const uint2* b = bring[ks % 3];
#pragma unroll
            for (int nt = 0; nt < 4; nt++)
#pragma unroll
                for (int mt = 0; mt < 4; mt++)
                    mma16(acc[mt][nt], (const uint32_t*)&a[mt], b[nt].x, b[nt].y);

            if (ks == 11) {
                if (ct != NT256 - 1) {
#pragma unroll
                    for (int mt = 0; mt < 4; mt++)
#pragma unroll
                        for (int nt = 0; nt < 4; nt++) {
                            rsum[mt][0] += exp_s(acc[mt][nt][0]) + exp_s(acc[mt][nt][1]);
                            rsum[mt][1] += exp_s(acc[mt][nt][2]) + exp_s(acc[mt][nt][3]);
                        }
                } else {
#pragma unroll
                    for (int mt = 0; mt < 4; mt++)
#pragma unroll
                        for (int nt = 0; nt < 4; nt++) {
                            int cls0 = ct * B_CLS + wn * 32 + nt * 8 + 2 * qt;
                            if (cls0 < C_CLS)     { rsum[mt][0] += exp_s(acc[mt][nt][0]);
                                                    rsum[mt][1] += exp_s(acc[mt][nt][2]); }
                            if (cls0 + 1 < C_CLS) { rsum[mt][0] += exp_s(acc[mt][nt][1]);
                                                    rsum[mt][1] += exp_s(acc[mt][nt][3]); }
                        }
                }
            }
        }
    }

    // ---- one partial per (stripe, wn) per row ----
    const int cidx = blockIdx.x * 8 + wn;
#pragma unroll
    for (int mt = 0; mt < 4; mt++) {
        float sLo = rsum[mt][0], sHi = rsum[mt][1];
        sLo += __shfl_xor_sync(0xffffffffu, sLo, 1);
        sLo += __shfl_xor_sync(0xffffffffu, sLo, 2);
        sHi += __shfl_xor_sync(0xffffffffu, sHi, 1);
        sHi += __shfl_xor_sync(0xffffffffu, sHi, 2);
        if (qt == 0) {
            int row = rowBase + wm * 64 + mt * 16 + qid;
            g_psum[(size_t)row * NPART + cidx]       = sLo;
            g_psum[(size_t)(row + 8) * NPART + cidx] = sHi;
        }
    }
}

// ---------------------------------------------------------------------------
// Kernel 3: warp per row: sum 296 partials + margin correction
// ---------------------------------------------------------------------------
__global__ void combine_kernel() {
    int row  = blockIdx.x * 8 + (threadIdx.x >> 5);
    int lane = threadIdx.x & 31;
    const float* p = g_psum + (size_t)row * NPART;
    float s = 0.f;
    for (int c = lane; c < NPART; c += 32) s += p[c];
#pragma unroll
    for (int o = 16; o; o >>= 1) s += __shfl_xor_sync(0xffffffffu, s, o);
    if (lane == 0) {
        float tgt   = g_tgt[row];
        float numer = S_SCALE * (tgt - MARGIN);
        float scorr = s - expf(S_SCALE * tgt) + expf(numer);
        g_L[row] = numer - logf(scorr);
    }
}

// ---------------------------------------------------------------------------
// Kernel 4: mean
// ---------------------------------------------------------------------------
__global__ void final_kernel(float* __restrict__ out) {
    __shared__ float sm[1024];
    int t = threadIdx.x;
    sm[t] = g_L[t] + g_L[t + 1024];
    __syncthreads();
    for (int st = 512; st > 0; st >>= 1) {
        if (t < st) sm[t] += sm[t + st];
        __syncthreads();
    }
    if (t == 0) out[0] = -sm[0] / (float)N_ROWS;
}

// ---------------------------------------------------------------------------
extern "C" void kernel_launch(void* const* d_in, const int* in_sizes, int n_in,
                              void* d_out, int out_size) {
    (void)in_sizes; (void)n_in; (void)out_size;
    const float* x     = (const float*)d_in[0];
    const float* W     = (const float*)d_in[1];
    const void*  label = d_in[2];
    float* out = (float*)d_out;

    detect_label_kernel<<<1, 256>>>((const int*)label);
    convertW_kernel<<<(CPAD * 12 + 255) / 256, 256>>>(W);
    norm_tgt_kernel<<<N_ROWS / 8, 256>>>(x, W, label);

    dim3 grid(STRIPES, N_ROWS / 128);
    gemm_lse_mma<<<grid, 512>>>();

    combine_kernel<<<N_ROWS / 8, 256>>>();
    final_kernel<<<1, 1024>>>(out);
}

// round 14
// speedup vs baseline: 1.3497x; 1.0081x over previous
#include <cuda_runtime.h>
#include <math.h>
#include <stdint.h>

// Problem constants
#define N_ROWS 2048
#define D_DIM  192
#define C_CLS  100000
#define S_SCALE 30.0f
#define MARGIN  0.2f
#define SC_LOG2E 43.2808512266689f   // S * log2(e)

#define NT256 391         // class tiles of 256 (391*256 = 100096)
#define CPAD  100096
#define NGRP  (CPAD / 8)  // 12512 class-groups of 8
#define STRIPES 37        // grid (37,16) = 592 CTAs = 4 waves @ 1 CTA/SM (512 thr)
#define NPART (STRIPES * 8)   // 296 partials per row
#define B_CLS 256

// ---------------- scratch globals ----------------
// g_xn holds xn * SC_LOG2E (scale folded into A so epilogue is bare ex2)
__device__ __align__(16) float g_xn[N_ROWS * D_DIM];
// B bf16, kp-fragment-contiguous: uint4 idx = ((grp8*6 + kp)*8 + cls8)*4 + qt
// holds {ks=2kp:(b0,b1), ks=2kp+1:(b0,b1)}; warp fragment-pair = 32 consecutive
// uint4 = 512 B = one LDG.128 per warp.
__device__ __align__(16) uint2 g_wb2[(size_t)NGRP * 6 * 64];
__device__ float g_tgt[N_ROWS];
__device__ float g_psum[(size_t)N_ROWS * NPART];
__device__ float g_L[N_ROWS];
__device__ int   g_lab32;

// ---------------- helpers (sm_80-level PTX only) ----------------
// pack(lo, hi): bf16x2 register {hi:lo}
__device__ __forceinline__ uint32_t bfpack(float lo, float hi) {
    uint32_t r;
    asm("cvt.rn.bf16x2.f32 %0, %1, %2;" : "=r"(r) : "f"(hi), "f"(lo));
    return r;
}

__device__ __forceinline__ void mma16(float* c, const uint32_t* a, uint32_t b0, uint32_t b1) {
    asm volatile(
        "mma.sync.aligned.m16n8k16.row.col.f32.bf16.bf16.f32 "
        "{%0,%1,%2,%3}, {%4,%5,%6,%7}, {%8,%9}, {%0,%1,%2,%3};"
        : "+f"(c[0]), "+f"(c[1]), "+f"(c[2]), "+f"(c[3])
        : "r"(a[0]), "r"(a[1]), "r"(a[2]), "r"(a[3]), "r"(b0), "r"(b1));
}

// bare ex2 — acc already carries S*log2(e) scaling
__device__ __forceinline__ float ex2(float d) {
    float r;
    asm("ex2.approx.f32 %0, %1;" : "=f"(r) : "f"(d));
    return r;
}

// ---------------------------------------------------------------------------
// Kernel 0: label dtype detect (touches only first 8KB; safe either way)
// ---------------------------------------------------------------------------
__global__ void detect_label_kernel(const int* __restrict__ lab) {
    __shared__ int any;
    if (threadIdx.x == 0) any = 0;
    __syncthreads();
    int v = 0;
    for (int i = threadIdx.x; i < 1024; i += blockDim.x) v |= lab[2 * i + 1];
    if (v) atomicOr(&any, 1);
    __syncthreads();
    if (threadIdx.x == 0) g_lab32 = (any != 0) ? 1 : 0;
}

// ---------------------------------------------------------------------------
// Kernel 0b: W (f32) -> g_wb2 (bf16), kp-fragment-contiguous layout.
// Thread handles one (cls, ks); qt word pair = k-pairs {2qt,2qt+1},{2qt+8,2qt+9}.
// uint2 index = (((cls/8)*6 + ks/2)*32 + (cls%8)*4 + qt)*2 + (ks&1).
// ---------------------------------------------------------------------------
__global__ void convertW_kernel(const float* __restrict__ W) {
    int idx = blockIdx.x * blockDim.x + threadIdx.x;   // (cls, ks) pair
    if (idx >= CPAD * 12) return;
    int cls = idx / 12, ks = idx % 12;
    int cr = cls < C_CLS ? cls : C_CLS - 1;
    const float* wr = W + (size_t)cr * D_DIM + ks * 16;
    float v[16];
#pragma unroll
    for (int j = 0; j < 4; j++) {
        float4 t = ((const float4*)wr)[j];
        v[4 * j] = t.x; v[4 * j + 1] = t.y; v[4 * j + 2] = t.z; v[4 * j + 3] = t.w;
    }
    const int ps[8] = {0, 8, 2, 10, 4, 12, 6, 14};   // qt-word k-pair order
    size_t base = (((size_t)(cls >> 3) * 6 + (ks >> 1)) * 32 + (cls & 7) * 4) * 2 + (ks & 1);
#pragma unroll
    for (int qt = 0; qt < 4; qt++) {
        uint2 o2;
        o2.x = bfpack(v[ps[2 * qt]],     v[ps[2 * qt] + 1]);
        o2.y = bfpack(v[ps[2 * qt + 1]], v[ps[2 * qt + 1] + 1]);
        g_wb2[base + qt * 2] = o2;
    }
}

// ---------------------------------------------------------------------------
// Kernel 1: row normalize (scaled by S*log2e) + exact target logit (fp32)
// ---------------------------------------------------------------------------
__global__ void norm_tgt_kernel(const float* __restrict__ x,
                                const float* __restrict__ W,
                                const void* __restrict__ label) {
    int warp = (blockIdx.x * blockDim.x + threadIdx.x) >> 5;
    int lane = threadIdx.x & 31;
    if (warp >= N_ROWS) return;

    const float* xr = x + (size_t)warp * D_DIM;
    float xv[6], ss = 0.f;
#pragma unroll
    for (int j = 0; j < 6; j++) { xv[j] = xr[lane + 32 * j]; ss += xv[j] * xv[j]; }
#pragma unroll
    for (int o = 16; o; o >>= 1) ss += __shfl_xor_sync(0xffffffffu, ss, o);
    float inv = rsqrtf(ss);

    long long li = g_lab32 ? (long long)((const int*)label)[warp]
                           : ((const long long*)label)[warp];
    if (li < 0) li = 0;
    if (li >= C_CLS) li = C_CLS - 1;

    const float* wr = W + (size_t)li * D_DIM;
    float dot = 0.f;
#pragma unroll
    for (int j = 0; j < 6; j++) {
        g_xn[(size_t)warp * D_DIM + lane + 32 * j] = xv[j] * inv * SC_LOG2E;
        dot += xv[j] * wr[lane + 32 * j];
    }
#pragma unroll
    for (int o = 16; o; o >>= 1) dot += __shfl_xor_sync(0xffffffffu, dot, o);
    if (lane == 0) g_tgt[warp] = dot * inv;
}

// ---------------------------------------------------------------------------
// Kernel 2: bf16 mma.sync m16n8k16 GEMM, 128 rows x 256 classes per tile.
// B streamed gmem->registers, ONE 512B LDG.128 per warp fragment-PAIR (2 ks).
// 2-slot kp prefetch ring, no barriers in the main loop, 16 warps free-run.
// Epilogue: bare ex2 (scale pre-folded into A).
//   warp grid 2(m) x 8(n); warp tile 64x32; 4(mt) x 4(nt) fragments.
// ---------------------------------------------------------------------------
__global__ void __launch_bounds__(512, 1) gemm_lse_mma() {
    __shared__ uint4 As4[96 * 32];        // [96 frags][32 lanes] = 48 KB

    const int tid  = threadIdx.x;
    const int wid  = tid >> 5;
    const int lane = tid & 31;
    const int wm = wid >> 3, wn = wid & 7;
    const int qid = lane >> 2, qt = lane & 3;
    const int rowBase = blockIdx.y * 128;
    const int ct0 = blockIdx.x;

    // ---- stage A once as bf16 m16n8k16 fragments (pre-scaled values) ----
    for (int f = wid; f < 96; f += 16) {
        int fm = f / 12, ks = f % 12;
        const float* b0 = g_xn + (size_t)(rowBase + fm * 16 + qid) * D_DIM + ks * 16 + 2 * qt;
        const float* b8 = b0 + 8 * D_DIM;
        As4[f * 32 + lane] = make_uint4(
            bfpack(b0[0], b0[1]), bfpack(b8[0], b8[1]),
            bfpack(b0[8], b0[9]), bfpack(b8[8], b8[9]));
    }
    __syncthreads();      // the only block barrier

    const uint4* __restrict__ gw4 = (const uint4*)g_wb2;
    const int ntiles = (NT256 - 1 - ct0) / STRIPES + 1;

    // Coalesced B fragment-pair fetch: one LDG.128 per nt.
    auto fetchB = [&](uint4* dst, int ct, int kp) {
        size_t base = (((size_t)(ct * 32 + wn * 4)) * 6 + kp) * 32 + lane;
#pragma unroll
        for (int nt = 0; nt < 4; nt++)
            dst[nt] = gw4[base + (size_t)nt * 6 * 32];
    };

    uint4 bring[2][4];    // 2-slot kp ring
    fetchB(bring[0], ct0, 0);

    float rsum[4][2] = {};
    float acc[4][4][4];

    const uint4* af0 = As4 + (wm * 4) * 12 * 32 + lane;

    for (int t = 0; t < ntiles; t++) {
        const int ct  = ct0 + t * STRIPES;
        const int ctn = (t + 1 < ntiles) ? ct + STRIPES : ct;

#pragma unroll
        for (int kp = 0; kp < 6; kp++) {
            // prefetch next kp (or next tile's kp 0) into the other slot
            if (kp < 5)      fetchB(bring[(kp + 1) & 1], ct, kp + 1);
            else             fetchB(bring[(kp + 1) & 1], ctn, 0);

            if (kp == 0) {
#pragma unroll
                for (int mt = 0; mt < 4; mt++)
#pragma unroll
                    for (int nt = 0; nt < 4; nt++)
#pragma unroll
                        for (int e = 0; e < 4; e++) acc[mt][nt][e] = 0.f;
            }

            const uint4* b = bring[kp & 1];
#pragma unroll
            for (int ksin = 0; ksin < 2; ksin++) {
                const int ks = 2 * kp + ksin;
#pragma unroll
                for (int mt = 0; mt < 4; mt++) {
                    uint4 a = af0[(mt * 12 + ks) * 32];
#pragma unroll
                    for (int nt = 0; nt < 4; nt++)
                        mma16(acc[mt][nt], (const uint32_t*)&a,
                              ksin ? b[nt].z : b[nt].x,
                              ksin ? b[nt].w : b[nt].y);
                }
            }

            if (kp == 5) {
                if (ct != NT256 - 1) {
#pragma unroll
                    for (int mt = 0; mt < 4; mt++)
#pragma unroll
                        for (int nt = 0; nt < 4; nt++) {
                            rsum[mt][0] += ex2(acc[mt][nt][0]) + ex2(acc[mt][nt][1]);
                            rsum[mt][1] += ex2(acc[mt][nt][2]) + ex2(acc[mt][nt][3]);
                        }
                } else {
#pragma unroll
                    for (int mt = 0; mt < 4; mt++)
#pragma unroll
                        for (int nt = 0; nt < 4; nt++) {
                            int cls0 = ct * B_CLS + wn * 32 + nt * 8 + 2 * qt;
                            if (cls0 < C_CLS)     { rsum[mt][0] += ex2(acc[mt][nt][0]);
                                                    rsum[mt][1] += ex2(acc[mt][nt][2]); }
                            if (cls0 + 1 < C_CLS) { rsum[mt][0] += ex2(acc[mt][nt][1]);
                                                    rsum[mt][1] += ex2(acc[mt][nt][3]); }
                        }
                }
            }
        }
    }

    // ---- one partial per (stripe, wn) per row ----
    const int cidx = blockIdx.x * 8 + wn;
#pragma unroll
    for (int mt = 0; mt < 4; mt++) {
        float sLo = rsum[mt][0], sHi = rsum[mt][1];
        sLo += __shfl_xor_sync(0xffffffffu, sLo, 1);
        sLo += __shfl_xor_sync(0xffffffffu, sLo, 2);
        sHi += __shfl_xor_sync(0xffffffffu, sHi, 1);
        sHi += __shfl_xor_sync(0xffffffffu, sHi, 2);
        if (qt == 0) {
            int row = rowBase + wm * 64 + mt * 16 + qid;
            g_psum[(size_t)row * NPART + cidx]       = sLo;
            g_psum[(size_t)(row + 8) * NPART + cidx] = sHi;
        }
    }
}

// ---------------------------------------------------------------------------
// Kernel 3: warp per row: sum 296 partials + margin correction
// ---------------------------------------------------------------------------
__global__ void combine_kernel() {
    int row  = blockIdx.x * 8 + (threadIdx.x >> 5);
    int lane = threadIdx.x & 31;
    const float* p = g_psum + (size_t)row * NPART;
    float s = 0.f;
    for (int c = lane; c < NPART; c += 32) s += p[c];
#pragma unroll
    for (int o = 16; o; o >>= 1) s += __shfl_xor_sync(0xffffffffu, s, o);
    if (lane == 0) {
        float tgt   = g_tgt[row];
        float numer = S_SCALE * (tgt - MARGIN);
        float scorr = s - expf(S_SCALE * tgt) + expf(numer);
        g_L[row] = numer - logf(scorr);
    }
}

// ---------------------------------------------------------------------------
// Kernel 4: mean
// ---------------------------------------------------------------------------
__global__ void final_kernel(float* __restrict__ out) {
    __shared__ float sm[1024];
    int t = threadIdx.x;
    sm[t] = g_L[t] + g_L[t + 1024];
    __syncthreads();
    for (int st = 512; st > 0; st >>= 1) {
        if (t < st) sm[t] += sm[t + st];
        __syncthreads();
    }
    if (t == 0) out[0] = -sm[0] / (float)N_ROWS;
}

// ---------------------------------------------------------------------------
extern "C" void kernel_launch(void* const* d_in, const int* in_sizes, int n_in,
                              void* d_out, int out_size) {
    (void)in_sizes; (void)n_in; (void)out_size;
    const float* x     = (const float*)d_in[0];
    const float* W     = (const float*)d_in[1];
    const void*  label = d_in[2];
    float* out = (float*)d_out;

    detect_label_kernel<<<1, 256>>>((const int*)label);
    convertW_kernel<<<(CPAD * 12 + 255) / 256, 256>>>(W);
    norm_tgt_kernel<<<N_ROWS / 8, 256>>>(x, W, label);

    dim3 grid(STRIPES, N_ROWS / 128);
    gemm_lse_mma<<<grid, 512>>>();

    combine_kernel<<<N_ROWS / 8, 256>>>();
    final_kernel<<<1, 1024>>>(out);
}

// round 15
// speedup vs baseline: 1.3895x; 1.0295x over previous
#include <cuda_runtime.h>
#include <cuda_fp16.h>
#include <math.h>
#include <stdint.h>

// Problem constants
#define N_ROWS 2048
#define D_DIM  192
#define C_CLS  100000
#define S_SCALE 30.0f
#define MARGIN  0.2f
#define SC_LOG2E 43.2808512266689f   // S * log2(e)

#define NT256 391         // class tiles of 256 (391*256 = 100096)
#define CPAD  100096
#define NGRP  (CPAD / 8)  // 12512 class-groups of 8
#define STRIPES 37        // grid (37,16) = 592 CTAs = 4 waves @ 1 CTA/SM (512 thr)
#define NPART (STRIPES * 8)   // 296 partials per row
#define B_CLS 256

// ---------------- scratch globals ----------------
// g_xn holds xn * SC_LOG2E (scale folded into A so epilogue is bare ex2)
__device__ __align__(16) float g_xn[N_ROWS * D_DIM];
// B fp16, kp-fragment-contiguous: uint4 idx = ((grp8*6 + kp)*8 + cls8)*4 + qt
// holds {ks=2kp:(b0,b1), ks=2kp+1:(b0,b1)}; warp fragment-pair = 32 consecutive
// uint4 = 512 B = one LDG.128 per warp.
__device__ __align__(16) uint2 g_wh2[(size_t)NGRP * 6 * 64];
__device__ float g_tgt[N_ROWS];
__device__ float g_psum[(size_t)N_ROWS * NPART];
__device__ float g_L[N_ROWS];
__device__ int   g_lab32;

// ---------------- helpers (sm_80-level PTX only) ----------------
// pack(lo, hi) -> f16x2 register {hi:lo}
__device__ __forceinline__ uint32_t hpack(float lo, float hi) {
    __half2 h = __floats2half2_rn(lo, hi);
    return *(uint32_t*)&h;
}

// m16n8k16 f16 x f16 -> f16 accumulators (2 regs = 4 halves)
__device__ __forceinline__ void mma16h(uint2* c, const uint32_t* a, uint32_t b0, uint32_t b1) {
    asm volatile(
        "mma.sync.aligned.m16n8k16.row.col.f16.f16.f16.f16 "
        "{%0,%1}, {%2,%3,%4,%5}, {%6,%7}, {%0,%1};"
        : "+r"(c->x), "+r"(c->y)
        : "r"(a[0]), "r"(a[1]), "r"(a[2]), "r"(a[3]), "r"(b0), "r"(b1));
}

// bare ex2 — acc already carries S*log2(e) scaling. ex2(-inf) = 0.
__device__ __forceinline__ float ex2(float d) {
    float r;
    asm("ex2.approx.f32 %0, %1;" : "=f"(r) : "f"(d));
    return r;
}

// ---------------------------------------------------------------------------
// Kernel 0: label dtype detect (touches only first 8KB; safe either way)
// ---------------------------------------------------------------------------
__global__ void detect_label_kernel(const int* __restrict__ lab) {
    __shared__ int any;
    if (threadIdx.x == 0) any = 0;
    __syncthreads();
    int v = 0;
    for (int i = threadIdx.x; i < 1024; i += blockDim.x) v |= lab[2 * i + 1];
    if (v) atomicOr(&any, 1);
    __syncthreads();
    if (threadIdx.x == 0) g_lab32 = (any != 0) ? 1 : 0;
}

// ---------------------------------------------------------------------------
// Kernel 0b: W (f32) -> g_wh2 (fp16), kp-fragment-contiguous layout.
// Thread handles one (cls, ks); qt word pair = k-pairs {2qt,2qt+1},{2qt+8,2qt+9}.
// uint2 index = (((cls/8)*6 + ks/2)*32 + (cls%8)*4 + qt)*2 + (ks&1).
// ---------------------------------------------------------------------------
__global__ void convertW_kernel(const float* __restrict__ W) {
    int idx = blockIdx.x * blockDim.x + threadIdx.x;   // (cls, ks) pair
    if (idx >= CPAD * 12) return;
    int cls = idx / 12, ks = idx % 12;
    int cr = cls < C_CLS ? cls : C_CLS - 1;
    const float* wr = W + (size_t)cr * D_DIM + ks * 16;
    float v[16];
#pragma unroll
    for (int j = 0; j < 4; j++) {
        float4 t = ((const float4*)wr)[j];
        v[4 * j] = t.x; v[4 * j + 1] = t.y; v[4 * j + 2] = t.z; v[4 * j + 3] = t.w;
    }
    const int ps[8] = {0, 8, 2, 10, 4, 12, 6, 14};   // qt-word k-pair order
    size_t base = (((size_t)(cls >> 3) * 6 + (ks >> 1)) * 32 + (cls & 7) * 4) * 2 + (ks & 1);
#pragma unroll
    for (int qt = 0; qt < 4; qt++) {
        uint2 o2;
        o2.x = hpack(v[ps[2 * qt]],     v[ps[2 * qt] + 1]);
        o2.y = hpack(v[ps[2 * qt + 1]], v[ps[2 * qt + 1] + 1]);
        g_wh2[base + qt * 2] = o2;
    }
}

// ---------------------------------------------------------------------------
// Kernel 1: row normalize (scaled by S*log2e) + exact target logit (fp32)
// ---------------------------------------------------------------------------
__global__ void norm_tgt_kernel(const float* __restrict__ x,
                                const float* __restrict__ W,
                                const void* __restrict__ label) {
    int warp = (blockIdx.x * blockDim.x + threadIdx.x) >> 5;
    int lane = threadIdx.x & 31;
    if (warp >= N_ROWS) return;

    const float* xr = x + (size_t)warp * D_DIM;
    float xv[6], ss = 0.f;
#pragma unroll
    for (int j = 0; j < 6; j++) { xv[j] = xr[lane + 32 * j]; ss += xv[j] * xv[j]; }
#pragma unroll
    for (int o = 16; o; o >>= 1) ss += __shfl_xor_sync(0xffffffffu, ss, o);
    float inv = rsqrtf(ss);

    long long li = g_lab32 ? (long long)((const int*)label)[warp]
                           : ((const long long*)label)[warp];
    if (li < 0) li = 0;
    if (li >= C_CLS) li = C_CLS - 1;

    const float* wr = W + (size_t)li * D_DIM;
    float dot = 0.f;
#pragma unroll
    for (int j = 0; j < 6; j++) {
        g_xn[(size_t)warp * D_DIM + lane + 32 * j] = xv[j] * inv * SC_LOG2E;
        dot += xv[j] * wr[lane + 32 * j];
    }
#pragma unroll
    for (int o = 16; o; o >>= 1) dot += __shfl_xor_sync(0xffffffffu, dot, o);
    if (lane == 0) g_tgt[warp] = dot * inv;
}

// ---------------------------------------------------------------------------
// Kernel 2: fp16 mma.sync m16n8k16 (f16 accumulators), 128 x 256 per tile.
// B streamed gmem->registers (one 512B LDG.128 per fragment-pair, 2-slot kp
// ring). Previous tile's accumulators stashed in the 32 regs freed by f16
// acc; their ex2 is SPREAD across the next tile's kp slots — no MUFU burst.
// No barriers in the main loop; 16 warps free-running.
//   warp grid 2(m) x 8(n); warp tile 64x32; 4(mt) x 4(nt) fragments.
// ---------------------------------------------------------------------------
__global__ void __launch_bounds__(512, 1) gemm_lse_mma() {
    __shared__ uint4 As4[96 * 32];        // [96 frags][32 lanes] = 48 KB

    const int tid  = threadIdx.x;
    const int wid  = tid >> 5;
    const int lane = tid & 31;
    const int wm = wid >> 3, wn = wid & 7;
    const int qid = lane >> 2, qt = lane & 3;
    const int rowBase = blockIdx.y * 128;
    const int ct0 = blockIdx.x;

    // ---- stage A once as fp16 m16n8k16 fragments (pre-scaled values) ----
    for (int f = wid; f < 96; f += 16) {
        int fm = f / 12, ks = f % 12;
        const float* b0 = g_xn + (size_t)(rowBase + fm * 16 + qid) * D_DIM + ks * 16 + 2 * qt;
        const float* b8 = b0 + 8 * D_DIM;
        As4[f * 32 + lane] = make_uint4(
            hpack(b0[0], b0[1]), hpack(b8[0], b8[1]),
            hpack(b0[8], b0[9]), hpack(b8[8], b8[9]));
    }
    __syncthreads();      // the only block barrier

    const uint4* __restrict__ gw4 = (const uint4*)g_wh2;
    const int ntiles = (NT256 - 1 - ct0) / STRIPES + 1;

    // Coalesced B fragment-pair fetch: one LDG.128 per nt.
    auto fetchB = [&](uint4* dst, int ct, int kp) {
        size_t base = (((size_t)(ct * 32 + wn * 4)) * 6 + kp) * 32 + lane;
#pragma unroll
        for (int nt = 0; nt < 4; nt++)
            dst[nt] = gw4[base + (size_t)nt * 6 * 32];
    };

    uint4 bring[2][4];    // 2-slot kp ring
    fetchB(bring[0], ct0, 0);

    float rsum[4][2] = {};
    uint2 acc[16];        // f16x2 accumulators, [mt*4+nt]
    uint2 stash[16];      // previous tile's accs; -inf halves -> ex2 = 0
#pragma unroll
    for (int e = 0; e < 16; e++) {
        acc[e]   = make_uint2(0u, 0u);
        stash[e] = make_uint2(0xFC00FC00u, 0xFC00FC00u);
    }

    const uint4* af0 = As4 + (wm * 4) * 12 * 32 + lane;

    for (int t = 0; t < ntiles; t++) {
        const int ct  = ct0 + t * STRIPES;
        const int ctn = (t + 1 < ntiles) ? ct + STRIPES : ct;

#pragma unroll
        for (int kp = 0; kp < 6; kp++) {
            // prefetch next kp (or next tile's kp 0) into the other slot
            if (kp < 5)      fetchB(bring[(kp + 1) & 1], ct, kp + 1);
            else             fetchB(bring[(kp + 1) & 1], ctn, 0);

            // spread previous tile's epilogue: 3 stash entries per kp slot
#pragma unroll
            for (int e = kp * 3; e < (kp == 5 ? 16 : kp * 3 + 3); e++) {
                float2 f0 = __half22float2(*(const __half2*)&stash[e].x);
                float2 f1 = __half22float2(*(const __half2*)&stash[e].y);
                rsum[e >> 2][0] += ex2(f0.x) + ex2(f0.y);
                rsum[e >> 2][1] += ex2(f1.x) + ex2(f1.y);
            }

            const uint4* b = bring[kp & 1];
#pragma unroll
            for (int ksin = 0; ksin < 2; ksin++) {
                const int ks = 2 * kp + ksin;
#pragma unroll
                for (int mt = 0; mt < 4; mt++) {
                    uint4 a = af0[(mt * 12 + ks) * 32];
#pragma unroll
                    for (int nt = 0; nt < 4; nt++)
                        mma16h(&acc[mt * 4 + nt], (const uint32_t*)&a,
                               ksin ? b[nt].z : b[nt].x,
                               ksin ? b[nt].w : b[nt].y);
                }
            }

            if (kp == 5) {
                // move accs to stash, clear for next tile
#pragma unroll
                for (int e = 0; e < 16; e++) {
                    stash[e] = acc[e];
                    acc[e]   = make_uint2(0u, 0u);
                }
            }
        }
    }

    // ---- flush the final tile's stash (with tail masking if padded tile) ----
    const int ctLast = ct0 + (ntiles - 1) * STRIPES;
    if (ctLast != NT256 - 1) {
#pragma unroll
        for (int e = 0; e < 16; e++) {
            float2 f0 = __half22float2(*(const __half2*)&stash[e].x);
            float2 f1 = __half22float2(*(const __half2*)&stash[e].y);
            rsum[e >> 2][0] += ex2(f0.x) + ex2(f0.y);
            rsum[e >> 2][1] += ex2(f1.x) + ex2(f1.y);
        }
    } else {
#pragma unroll
        for (int e = 0; e < 16; e++) {
            int nt = e & 3;
            int cls0 = ctLast * B_CLS + wn * 32 + nt * 8 + 2 * qt;
            float2 f0 = __half22float2(*(const __half2*)&stash[e].x);
            float2 f1 = __half22float2(*(const __half2*)&stash[e].y);
            if (cls0 < C_CLS)     { rsum[e >> 2][0] += ex2(f0.x);
                                    rsum[e >> 2][1] += ex2(f1.x); }
            if (cls0 + 1 < C_CLS) { rsum[e >> 2][0] += ex2(f0.y);
                                    rsum[e >> 2][1] += ex2(f1.y); }
        }
    }

    // ---- one partial per (stripe, wn) per row ----
    const int cidx = blockIdx.x * 8 + wn;
#pragma unroll
    for (int mt = 0; mt < 4; mt++) {
        float sLo = rsum[mt][0], sHi = rsum[mt][1];
        sLo += __shfl_xor_sync(0xffffffffu, sLo, 1);
        sLo += __shfl_xor_sync(0xffffffffu, sLo, 2);
        sHi += __shfl_xor_sync(0xffffffffu, sHi, 1);
        sHi += __shfl_xor_sync(0xffffffffu, sHi, 2);
        if (qt == 0) {
            int row = rowBase + wm * 64 + mt * 16 + qid;
            g_psum[(size_t)row * NPART + cidx]       = sLo;
            g_psum[(size_t)(row + 8) * NPART + cidx] = sHi;
        }
    }
}

// ---------------------------------------------------------------------------
// Kernel 3: warp per row: sum 296 partials + margin correction
// ---------------------------------------------------------------------------
__global__ void combine_kernel() {
    int row  = blockIdx.x * 8 + (threadIdx.x >> 5);
    int lane = threadIdx.x & 31;
    const float* p = g_psum + (size_t)row * NPART;
    float s = 0.f;
    for (int c = lane; c < NPART; c += 32) s += p[c];
#pragma unroll
    for (int o = 16; o; o >>= 1) s += __shfl_xor_sync(0xffffffffu, s, o);
    if (lane == 0) {
        float tgt   = g_tgt[row];
        float numer = S_SCALE * (tgt - MARGIN);
        float scorr = s - expf(S_SCALE * tgt) + expf(numer);
        g_L[row] = numer - logf(scorr);
    }
}

// ---------------------------------------------------------------------------
// Kernel 4: mean
// ---------------------------------------------------------------------------
__global__ void final_kernel(float* __restrict__ out) {
    __shared__ float sm[1024];
    int t = threadIdx.x;
    sm[t] = g_L[t] + g_L[t + 1024];
    __syncthreads();
    for (int st = 512; st > 0; st >>= 1) {
        if (t < st) sm[t] += sm[t + st];
        __syncthreads();
    }
    if (t == 0) out[0] = -sm[0] / (float)N_ROWS;
}

// ---------------------------------------------------------------------------
extern "C" void kernel_launch(void* const* d_in, const int* in_sizes, int n_in,
                              void* d_out, int out_size) {
    (void)in_sizes; (void)n_in; (void)out_size;
    const float* x     = (const float*)d_in[0];
    const float* W     = (const float*)d_in[1];
    const void*  label = d_in[2];
    float* out = (float*)d_out;

    detect_label_kernel<<<1, 256>>>((const int*)label);
    convertW_kernel<<<(CPAD * 12 + 255) / 256, 256>>>(W);
    norm_tgt_kernel<<<N_ROWS / 8, 256>>>(x, W, label);

    dim3 grid(STRIPES, N_ROWS / 128);
    gemm_lse_mma<<<grid, 512>>>();

    combine_kernel<<<N_ROWS / 8, 256>>>();
    final_kernel<<<1, 1024>>>(out);
}

// round 16
// speedup vs baseline: 1.4014x; 1.0085x over previous
#include <cuda_runtime.h>
#include <cuda_fp16.h>
#include <math.h>
#include <stdint.h>

// Problem constants
#define N_ROWS 2048
#define D_DIM  192
#define C_CLS  100000
#define S_SCALE 30.0f
#define MARGIN  0.2f
#define SC_LOG2E 43.2808512266689f   // S * log2(e)

#define NT512 196         // class tiles of 512 (196*512 = 100352)
#define CPAD  (NT512 * 512)
#define NGRP  (CPAD / 8)  // 12544 class-groups of 8
#define STRIPES 98        // grid (98,32): every stripe = exactly 2 tiles
#define NPART (STRIPES * 8)   // 784 partials per row
#define B_CLS 512

// ---------------- scratch globals ----------------
// g_xn holds xn * SC_LOG2E (scale folded into A so epilogue is bare ex2)
__device__ __align__(16) float g_xn[N_ROWS * D_DIM];
// B fp16, ks-fragment-contiguous: uint2 idx = ((grp8*12 + ks)*8 + cls8)*4 + qt
// -> a warp's (nt,ks) fragment = 32 consecutive uint2 = 256B = one LDG.64.
__device__ __align__(16) uint2 g_wh2[(size_t)NGRP * 12 * 32];
__device__ float g_tgt[N_ROWS];
__device__ float g_psum[(size_t)N_ROWS * NPART];
__device__ float g_L[N_ROWS];
__device__ int   g_lab32;

// ---------------- helpers (sm_80-level PTX only) ----------------
// pack(lo, hi) -> f16x2 register {hi:lo}
__device__ __forceinline__ uint32_t hpack(float lo, float hi) {
    __half2 h = __floats2half2_rn(lo, hi);
    return *(uint32_t*)&h;
}

// m16n8k16 f16 x f16 -> f16 accumulators (2 regs = 4 halves)
__device__ __forceinline__ void mma16h(uint2* c, const uint32_t* a, uint32_t b0, uint32_t b1) {
    asm volatile(
        "mma.sync.aligned.m16n8k16.row.col.f16.f16.f16.f16 "
        "{%0,%1}, {%2,%3,%4,%5}, {%6,%7}, {%0,%1};"
        : "+r"(c->x), "+r"(c->y)
        : "r"(a[0]), "r"(a[1]), "r"(a[2]), "r"(a[3]), "r"(b0), "r"(b1));
}

// bare ex2 — acc already carries S*log2(e) scaling
__device__ __forceinline__ float ex2(float d) {
    float r;
    asm("ex2.approx.f32 %0, %1;" : "=f"(r) : "f"(d));
    return r;
}

// ---------------------------------------------------------------------------
// Kernel 0: label dtype detect (touches only first 8KB; safe either way)
// ---------------------------------------------------------------------------
__global__ void detect_label_kernel(const int* __restrict__ lab) {
    __shared__ int any;
    if (threadIdx.x == 0) any = 0;
    __syncthreads();
    int v = 0;
    for (int i = threadIdx.x; i < 1024; i += blockDim.x) v |= lab[2 * i + 1];
    if (v) atomicOr(&any, 1);
    __syncthreads();
    if (threadIdx.x == 0) g_lab32 = (any != 0) ? 1 : 0;
}

// ---------------------------------------------------------------------------
// Kernel 0b: W (f32) -> g_wh2 (fp16), ks-fragment-contiguous layout.
// Per (cls, ks): qt uint2 = {k-pairs (2qt,2qt+1), (2qt+8,2qt+9)}.
// uint2 index = ((cls/8)*12 + ks)*32 + (cls%8)*4 + qt.
// ---------------------------------------------------------------------------
__global__ void convertW_kernel(const float* __restrict__ W) {
    int idx = blockIdx.x * blockDim.x + threadIdx.x;   // (cls, ks) pair
    if (idx >= CPAD * 12) return;
    int cls = idx / 12, ks = idx % 12;
    int cr = cls < C_CLS ? cls : C_CLS - 1;
    const float* wr = W + (size_t)cr * D_DIM + ks * 16;
    float v[16];
#pragma unroll
    for (int j = 0; j < 4; j++) {
        float4 t = ((const float4*)wr)[j];
        v[4 * j] = t.x; v[4 * j + 1] = t.y; v[4 * j + 2] = t.z; v[4 * j + 3] = t.w;
    }
    const int ps[8] = {0, 8, 2, 10, 4, 12, 6, 14};   // qt-word k-pair order
    uint32_t o[8];
#pragma unroll
    for (int j = 0; j < 8; j++) o[j] = hpack(v[ps[j]], v[ps[j] + 1]);
    uint4* dst = (uint4*)(g_wh2 + ((size_t)(cls >> 3) * 12 + ks) * 32 + (cls & 7) * 4);
    dst[0] = make_uint4(o[0], o[1], o[2], o[3]);
    dst[1] = make_uint4(o[4], o[5], o[6], o[7]);
}

// ---------------------------------------------------------------------------
// Kernel 1: row normalize (scaled by S*log2e) + exact target logit (fp32)
// ---------------------------------------------------------------------------
__global__ void norm_tgt_kernel(const float* __restrict__ x,
                                const float* __restrict__ W,
                                const void* __restrict__ label) {
    int warp = (blockIdx.x * blockDim.x + threadIdx.x) >> 5;
    int lane = threadIdx.x & 31;
    if (warp >= N_ROWS) return;

    const float* xr = x + (size_t)warp * D_DIM;
    float xv[6], ss = 0.f;
#pragma unroll
    for (int j = 0; j < 6; j++) { xv[j] = xr[lane + 32 * j]; ss += xv[j] * xv[j]; }
#pragma unroll
    for (int o = 16; o; o >>= 1) ss += __shfl_xor_sync(0xffffffffu, ss, o);
    float inv = rsqrtf(ss);

    long long li = g_lab32 ? (long long)((const int*)label)[warp]
                           : ((const long long*)label)[warp];
    if (li < 0) li = 0;
    if (li >= C_CLS) li = C_CLS - 1;

    const float* wr = W + (size_t)li * D_DIM;
    float dot = 0.f;
#pragma unroll
    for (int j = 0; j < 6; j++) {
        g_xn[(size_t)warp * D_DIM + lane + 32 * j] = xv[j] * inv * SC_LOG2E;
        dot += xv[j] * wr[lane + 32 * j];
    }
#pragma unroll
    for (int o = 16; o; o >>= 1) dot += __shfl_xor_sync(0xffffffffu, dot, o);
    if (lane == 0) g_tgt[warp] = dot * inv;
}

// ---------------------------------------------------------------------------
// Kernel 2: fp16 mma.sync m16n8k16 (f16 acc), CTA tile 64 rows x 512 classes.
// Warp grid 1(m) x 8(n), warp tile 64x64 (4mt x 8nt): A LDS traffic per MMA
// halved vs 64x32, B has ZERO intra-CTA duplication. 256 threads, 2 CTAs/SM.
// B streamed gmem->registers (one 256B LDG.64 per fragment, 2-slot ks ring).
// Barrier-free main loop; each CTA runs exactly 2 class tiles (ct0, ct0+98).
// ---------------------------------------------------------------------------
__global__ void __launch_bounds__(256, 2) gemm_lse_mma() {
    __shared__ uint4 As4[48 * 32];        // [48 frags][32 lanes] = 24 KB

    const int tid  = threadIdx.x;
    const int wn   = tid >> 5;            // 0..7
    const int lane = tid & 31;
    const int qid = lane >> 2, qt = lane & 3;
    const int rowBase = blockIdx.y * 64;
    const int ct0 = blockIdx.x;

    // ---- stage A once as fp16 m16n8k16 fragments (pre-scaled values) ----
    // frag f = fm*12 + ks; fm = 16-row group (0..3), ks = k16 step (0..11)
    for (int f = wn; f < 48; f += 8) {
        int fm = f / 12, ks = f % 12;
        const float* b0 = g_xn + (size_t)(rowBase + fm * 16 + qid) * D_DIM + ks * 16 + 2 * qt;
        const float* b8 = b0 + 8 * D_DIM;
        As4[f * 32 + lane] = make_uint4(
            hpack(b0[0], b0[1]), hpack(b8[0], b8[1]),
            hpack(b0[8], b0[9]), hpack(b8[8], b8[9]));
    }
    __syncthreads();      // the only block barrier

    const uint2* __restrict__ gw = g_wh2;

    // Coalesced B fragment fetch: one 256B LDG.64 per nt; 8 nt per ks.
    auto fetchB = [&](uint2* dst, int ct, int ks) {
        size_t base = (((size_t)(ct * 64 + wn * 8)) * 12 + ks) * 32 + lane;
#pragma unroll
        for (int nt = 0; nt < 8; nt++)
            dst[nt] = gw[base + (size_t)nt * 12 * 32];
    };

    uint2 bring[2][8];    // 2-slot ks ring
    fetchB(bring[0], ct0, 0);

    float rsum[4][2] = {};
    uint2 acc[32];        // f16x2 accumulators, [mt*8+nt]

    const uint4* af0 = As4 + lane;

#pragma unroll
    for (int t = 0; t < 2; t++) {
        const int ct = ct0 + t * STRIPES;

#pragma unroll
        for (int ks = 0; ks < 12; ks++) {
            // prefetch next ks (or tile 2's ks 0) into the other slot
            if (ks < 11)      fetchB(bring[(ks + 1) & 1], ct, ks + 1);
            else if (t == 0)  fetchB(bring[(ks + 1) & 1], ct0 + STRIPES, 0);

            if (ks == 0) {
#pragma unroll
                for (int e = 0; e < 32; e++) acc[e] = make_uint2(0u, 0u);
            }

            const uint2* b = bring[ks & 1];
#pragma unroll
            for (int mt = 0; mt < 4; mt++) {
                uint4 a = af0[(mt * 12 + ks) * 32];
#pragma unroll
                for (int nt = 0; nt < 8; nt++)
                    mma16h(&acc[mt * 8 + nt], (const uint32_t*)&a, b[nt].x, b[nt].y);
            }

            if (ks == 11) {
                // ---- tile epilogue: sum exp2 of accumulators ----
                if (ct != NT512 - 1) {
#pragma unroll
                    for (int e = 0; e < 32; e++) {
                        float2 f0 = __half22float2(*(const __half2*)&acc[e].x);
                        float2 f1 = __half22float2(*(const __half2*)&acc[e].y);
                        rsum[e >> 3][0] += ex2(f0.x) + ex2(f0.y);
                        rsum[e >> 3][1] += ex2(f1.x) + ex2(f1.y);
                    }
                } else {
#pragma unroll
                    for (int e = 0; e < 32; e++) {
                        int nt = e & 7;
                        int cls0 = ct * B_CLS + wn * 64 + nt * 8 + 2 * qt;
                        float2 f0 = __half22float2(*(const __half2*)&acc[e].x);
                        float2 f1 = __half22float2(*(const __half2*)&acc[e].y);
                        if (cls0 < C_CLS)     { rsum[e >> 3][0] += ex2(f0.x);
                                                rsum[e >> 3][1] += ex2(f1.x); }
                        if (cls0 + 1 < C_CLS) { rsum[e >> 3][0] += ex2(f0.y);
                                                rsum[e >> 3][1] += ex2(f1.y); }
                    }
                }
            }
        }
    }

    // ---- one partial per (stripe, wn) per row ----
    const int cidx = blockIdx.x * 8 + wn;
#pragma unroll
    for (int mt = 0; mt < 4; mt++) {
        float sLo = rsum[mt][0], sHi = rsum[mt][1];
        sLo += __shfl_xor_sync(0xffffffffu, sLo, 1);
        sLo += __shfl_xor_sync(0xffffffffu, sLo, 2);
        sHi += __shfl_xor_sync(0xffffffffu, sHi, 1);
        sHi += __shfl_xor_sync(0xffffffffu, sHi, 2);
        if (qt == 0) {
            int row = rowBase + mt * 16 + qid;
            g_psum[(size_t)row * NPART + cidx]       = sLo;
            g_psum[(size_t)(row + 8) * NPART + cidx] = sHi;
        }
    }
}

// ---------------------------------------------------------------------------
// Kernel 3: warp per row: sum 784 partials + margin correction
// ---------------------------------------------------------------------------
__global__ void combine_kernel() {
    int row  = blockIdx.x * 8 + (threadIdx.x >> 5);
    int lane = threadIdx.x & 31;
    const float* p = g_psum + (size_t)row * NPART;
    float s = 0.f;
    for (int c = lane; c < NPART; c += 32) s += p[c];
#pragma unroll
    for (int o = 16; o; o >>= 1) s += __shfl_xor_sync(0xffffffffu, s, o);
    if (lane == 0) {
        float tgt   = g_tgt[row];
        float numer = S_SCALE * (tgt - MARGIN);
        float scorr = s - expf(S_SCALE * tgt) + expf(numer);
        g_L[row] = numer - logf(scorr);
    }
}

// ---------------------------------------------------------------------------
// Kernel 4: mean
// ---------------------------------------------------------------------------
__global__ void final_kernel(float* __restrict__ out) {
    __shared__ float sm[1024];
    int t = threadIdx.x;
    sm[t] = g_L[t] + g_L[t + 1024];
    __syncthreads();
    for (int st = 512; st > 0; st >>= 1) {
        if (t < st) sm[t] += sm[t + st];
        __syncthreads();
    }
    if (t == 0) out[0] = -sm[0] / (float)N_ROWS;
}

// ---------------------------------------------------------------------------
extern "C" void kernel_launch(void* const* d_in, const int* in_sizes, int n_in,
                              void* d_out, int out_size) {
    (void)in_sizes; (void)n_in; (void)out_size;
    const float* x     = (const float*)d_in[0];
    const float* W     = (const float*)d_in[1];
    const void*  label = d_in[2];
    float* out = (float*)d_out;

    detect_label_kernel<<<1, 256>>>((const int*)label);
    convertW_kernel<<<(CPAD * 12 + 255) / 256, 256>>>(W);
    norm_tgt_kernel<<<N_ROWS / 8, 256>>>(x, W, label);

    dim3 grid(STRIPES, N_ROWS / 64);
    gemm_lse_mma<<<grid, 256>>>();

    combine_kernel<<<N_ROWS / 8, 256>>>();
    final_kernel<<<1, 1024>>>(out);
}

// round 17
// speedup vs baseline: 1.4717x; 1.0502x over previous
#include <cuda_runtime.h>
#include <cuda_fp16.h>
#include <math.h>
#include <stdint.h>

// Problem constants
#define N_ROWS 2048
#define D_DIM  192
#define C_CLS  100000
#define S_SCALE 30.0f
#define MARGIN  0.2f
#define SC_LOG2E 43.2808512266689f   // S * log2(e)

#define NT512 196         // class tiles of 512 (196*512 = 100352)
#define CPAD  (NT512 * 512)
#define NGRP  (CPAD / 8)  // 12544 class-groups of 8
#define STRIPES 49        // grid (49,32): every stripe = exactly 4 tiles
#define NPART (STRIPES * 8)   // 392 partials per row
#define B_CLS 512

// ---------------- scratch globals ----------------
// g_xn holds xn * SC_LOG2E (scale folded into A so epilogue is bare ex2)
__device__ __align__(16) float g_xn[N_ROWS * D_DIM];
// B fp16, ks-fragment-contiguous: uint2 idx = ((grp8*12 + ks)*8 + cls8)*4 + qt
// -> a warp's (nt,ks) fragment = 32 consecutive uint2 = 256B = one LDG.64.
__device__ __align__(16) uint2 g_wh2[(size_t)NGRP * 12 * 32];
__device__ float g_tgt[N_ROWS];
__device__ float g_psum[(size_t)N_ROWS * NPART];
__device__ float g_L[N_ROWS];
__device__ int   g_lab32;

// ---------------- helpers (sm_80-level PTX only) ----------------
// pack(lo, hi) -> f16x2 register {hi:lo}
__device__ __forceinline__ uint32_t hpack(float lo, float hi) {
    __half2 h = __floats2half2_rn(lo, hi);
    return *(uint32_t*)&h;
}

// m16n8k16 f16 x f16 -> f16 accumulators (2 regs = 4 halves)
__device__ __forceinline__ void mma16h(uint2* c, const uint32_t* a, uint32_t b0, uint32_t b1) {
    asm volatile(
        "mma.sync.aligned.m16n8k16.row.col.f16.f16.f16.f16 "
        "{%0,%1}, {%2,%3,%4,%5}, {%6,%7}, {%0,%1};"
        : "+r"(c->x), "+r"(c->y)
        : "r"(a[0]), "r"(a[1]), "r"(a[2]), "r"(a[3]), "r"(b0), "r"(b1));
}

// paired exponential: ex2 of both f16 halves in ONE MUFU op
__device__ __forceinline__ float2 ex2h2(uint32_t h2) {
    uint32_t r;
    asm("ex2.approx.f16x2 %0, %1;" : "=r"(r) : "r"(h2));
    return __half22float2(*(const __half2*)&r);
}

// scalar f32 ex2 (tail-masked path)
__device__ __forceinline__ float ex2(float d) {
    float r;
    asm("ex2.approx.f32 %0, %1;" : "=f"(r) : "f"(d));
    return r;
}

// ---------------------------------------------------------------------------
// Kernel 0: label dtype detect (touches only first 8KB; safe either way)
// ---------------------------------------------------------------------------
__global__ void detect_label_kernel(const int* __restrict__ lab) {
    __shared__ int any;
    if (threadIdx.x == 0) any = 0;
    __syncthreads();
    int v = 0;
    for (int i = threadIdx.x; i < 1024; i += blockDim.x) v |= lab[2 * i + 1];
    if (v) atomicOr(&any, 1);
    __syncthreads();
    if (threadIdx.x == 0) g_lab32 = (any != 0) ? 1 : 0;
}

// ---------------------------------------------------------------------------
// Kernel 0b: W (f32) -> g_wh2 (fp16), ks-fragment-contiguous layout.
// Per (cls, ks): qt uint2 = {k-pairs (2qt,2qt+1), (2qt+8,2qt+9)}.
// uint2 index = ((cls/8)*12 + ks)*32 + (cls%8)*4 + qt.
// ---------------------------------------------------------------------------
__global__ void convertW_kernel(const float* __restrict__ W) {
    int idx = blockIdx.x * blockDim.x + threadIdx.x;   // (cls, ks) pair
    if (idx >= CPAD * 12) return;
    int cls = idx / 12, ks = idx % 12;
    int cr = cls < C_CLS ? cls : C_CLS - 1;
    const float* wr = W + (size_t)cr * D_DIM + ks * 16;
    float v[16];
#pragma unroll
    for (int j = 0; j < 4; j++) {
        float4 t = ((const float4*)wr)[j];
        v[4 * j] = t.x; v[4 * j + 1] = t.y; v[4 * j + 2] = t.z; v[4 * j + 3] = t.w;
    }
    const int ps[8] = {0, 8, 2, 10, 4, 12, 6, 14};   // qt-word k-pair order
    uint32_t o[8];
#pragma unroll
    for (int j = 0; j < 8; j++) o[j] = hpack(v[ps[j]], v[ps[j] + 1]);
    uint4* dst = (uint4*)(g_wh2 + ((size_t)(cls >> 3) * 12 + ks) * 32 + (cls & 7) * 4);
    dst[0] = make_uint4(o[0], o[1], o[2], o[3]);
    dst[1] = make_uint4(o[4], o[5], o[6], o[7]);
}

// ---------------------------------------------------------------------------
// Kernel 1: row normalize (scaled by S*log2e) + exact target logit (fp32)
// ---------------------------------------------------------------------------
__global__ void norm_tgt_kernel(const float* __restrict__ x,
                                const float* __restrict__ W,
                                const void* __restrict__ label) {
    int warp = (blockIdx.x * blockDim.x + threadIdx.x) >> 5;
    int lane = threadIdx.x & 31;
    if (warp >= N_ROWS) return;

    const float* xr = x + (size_t)warp * D_DIM;
    float xv[6], ss = 0.f;
#pragma unroll
    for (int j = 0; j < 6; j++) { xv[j] = xr[lane + 32 * j]; ss += xv[j] * xv[j]; }
#pragma unroll
    for (int o = 16; o; o >>= 1) ss += __shfl_xor_sync(0xffffffffu, ss, o);
    float inv = rsqrtf(ss);

    long long li = g_lab32 ? (long long)((const int*)label)[warp]
                           : ((const long long*)label)[warp];
    if (li < 0) li = 0;
    if (li >= C_CLS) li = C_CLS - 1;

    const float* wr = W + (size_t)li * D_DIM;
    float dot = 0.f;
#pragma unroll
    for (int j = 0; j < 6; j++) {
        g_xn[(size_t)warp * D_DIM + lane + 32 * j] = xv[j] * inv * SC_LOG2E;
        dot += xv[j] * wr[lane + 32 * j];
    }
#pragma unroll
    for (int o = 16; o; o >>= 1) dot += __shfl_xor_sync(0xffffffffu, dot, o);
    if (lane == 0) g_tgt[warp] = dot * inv;
}

// ---------------------------------------------------------------------------
// Kernel 2: fp16 mma.sync m16n8k16 (f16 acc), CTA tile 64 rows x 512 classes.
// Warp grid 1(m) x 8(n), warp tile 64x64. 256 threads, 2 CTAs/SM.
// B streamed gmem->registers (one 256B LDG.64 per fragment, 2-slot ks ring).
// Barrier-free main loop; each CTA runs exactly 4 class tiles (ct0 + 49t).
// Epilogue: paired ex2.approx.f16x2 — half the MUFU ops, no pre-convert.
// ---------------------------------------------------------------------------
__global__ void __launch_bounds__(256, 2) gemm_lse_mma() {
    __shared__ uint4 As4[48 * 32];        // [48 frags][32 lanes] = 24 KB

    const int tid  = threadIdx.x;
    const int wn   = tid >> 5;            // 0..7
    const int lane = tid & 31;
    const int qid = lane >> 2, qt = lane & 3;
    const int rowBase = blockIdx.y * 64;
    const int ct0 = blockIdx.x;

    // ---- stage A once as fp16 m16n8k16 fragments (pre-scaled values) ----
    // frag f = fm*12 + ks; fm = 16-row group (0..3), ks = k16 step (0..11)
    for (int f = wn; f < 48; f += 8) {
        int fm = f / 12, ks = f % 12;
        const float* b0 = g_xn + (size_t)(rowBase + fm * 16 + qid) * D_DIM + ks * 16 + 2 * qt;
        const float* b8 = b0 + 8 * D_DIM;
        As4[f * 32 + lane] = make_uint4(
            hpack(b0[0], b0[1]), hpack(b8[0], b8[1]),
            hpack(b0[8], b0[9]), hpack(b8[8], b8[9]));
    }
    __syncthreads();      // the only block barrier

    const uint2* __restrict__ gw = g_wh2;

    // Coalesced B fragment fetch: one 256B LDG.64 per nt; 8 nt per ks.
    auto fetchB = [&](uint2* dst, int ct, int ks) {
        size_t base = (((size_t)(ct * 64 + wn * 8)) * 12 + ks) * 32 + lane;
#pragma unroll
        for (int nt = 0; nt < 8; nt++)
            dst[nt] = gw[base + (size_t)nt * 12 * 32];
    };

    uint2 bring[2][8];    // 2-slot ks ring
    fetchB(bring[0], ct0, 0);

    float rsum[4][2] = {};
    uint2 acc[32];        // f16x2 accumulators, [mt*8+nt]

    const uint4* af0 = As4 + lane;

#pragma unroll
    for (int t = 0; t < 4; t++) {
        const int ct = ct0 + t * STRIPES;

#pragma unroll
        for (int ks = 0; ks < 12; ks++) {
            // prefetch next ks (or next tile's ks 0) into the other slot
            if (ks < 11)      fetchB(bring[(ks + 1) & 1], ct, ks + 1);
            else if (t < 3)   fetchB(bring[(ks + 1) & 1], ct + STRIPES, 0);

            if (ks == 0) {
#pragma unroll
                for (int e = 0; e < 32; e++) acc[e] = make_uint2(0u, 0u);
            }

            const uint2* b = bring[ks & 1];
#pragma unroll
            for (int mt = 0; mt < 4; mt++) {
                uint4 a = af0[(mt * 12 + ks) * 32];
#pragma unroll
                for (int nt = 0; nt < 8; nt++)
                    mma16h(&acc[mt * 8 + nt], (const uint32_t*)&a, b[nt].x, b[nt].y);
            }

            if (ks == 11) {
                // ---- tile epilogue: paired f16x2 ex2 ----
                if (ct != NT512 - 1) {
#pragma unroll
                    for (int e = 0; e < 32; e++) {
                        float2 f0 = ex2h2(acc[e].x);
                        float2 f1 = ex2h2(acc[e].y);
                        rsum[e >> 3][0] += f0.x + f0.y;
                        rsum[e >> 3][1] += f1.x + f1.y;
                    }
                } else {
#pragma unroll
                    for (int e = 0; e < 32; e++) {
                        int nt = e & 7;
                        int cls0 = ct * B_CLS + wn * 64 + nt * 8 + 2 * qt;
                        float2 f0 = __half22float2(*(const __half2*)&acc[e].x);
                        float2 f1 = __half22float2(*(const __half2*)&acc[e].y);
                        if (cls0 < C_CLS)     { rsum[e >> 3][0] += ex2(f0.x);
                                                rsum[e >> 3][1] += ex2(f1.x); }
                        if (cls0 + 1 < C_CLS) { rsum[e >> 3][0] += ex2(f0.y);
                                                rsum[e >> 3][1] += ex2(f1.y); }
                    }
                }
            }
        }
    }

    // ---- one partial per (stripe, wn) per row ----
    const int cidx = blockIdx.x * 8 + wn;
#pragma unroll
    for (int mt = 0; mt < 4; mt++) {
        float sLo = rsum[mt][0], sHi = rsum[mt][1];
        sLo += __shfl_xor_sync(0xffffffffu, sLo, 1);
        sLo += __shfl_xor_sync(0xffffffffu, sLo, 2);
        sHi += __shfl_xor_sync(0xffffffffu, sHi, 1);
        sHi += __shfl_xor_sync(0xffffffffu, sHi, 2);
        if (qt == 0) {
            int row = rowBase + mt * 16 + qid;
            g_psum[(size_t)row * NPART + cidx]       = sLo;
            g_psum[(size_t)(row + 8) * NPART + cidx] = sHi;
        }
    }
}

// ---------------------------------------------------------------------------
// Kernel 3: warp per row: sum 392 partials + margin correction
// ---------------------------------------------------------------------------
__global__ void combine_kernel() {
    int row  = blockIdx.x * 8 + (threadIdx.x >> 5);
    int lane = threadIdx.x & 31;
    const float* p = g_psum + (size_t)row * NPART;
    float s = 0.f;
    for (int c = lane; c < NPART; c += 32) s += p[c];
#pragma unroll
    for (int o = 16; o; o >>= 1) s += __shfl_xor_sync(0xffffffffu, s, o);
    if (lane == 0) {
        float tgt   = g_tgt[row];
        float numer = S_SCALE * (tgt - MARGIN);
        float scorr = s - expf(S_SCALE * tgt) + expf(numer);
        g_L[row] = numer - logf(scorr);
    }
}

// ---------------------------------------------------------------------------
// Kernel 4: mean
// ---------------------------------------------------------------------------
__global__ void final_kernel(float* __restrict__ out) {
    __shared__ float sm[1024];
    int t = threadIdx.x;
    sm[t] = g_L[t] + g_L[t + 1024];
    __syncthreads();
    for (int st = 512; st > 0; st >>= 1) {
        if (t < st) sm[t] += sm[t + st];
        __syncthreads();
    }
    if (t == 0) out[0] = -sm[0] / (float)N_ROWS;
}

// ---------------------------------------------------------------------------
extern "C" void kernel_launch(void* const* d_in, const int* in_sizes, int n_in,
                              void* d_out, int out_size) {
    (void)in_sizes; (void)n_in; (void)out_size;
    const float* x     = (const float*)d_in[0];
    const float* W     = (const float*)d_in[1];
    const void*  label = d_in[2];
    float* out = (float*)d_out;

    detect_label_kernel<<<1, 256>>>((const int*)label);
    convertW_kernel<<<(CPAD * 12 + 255) / 256, 256>>>(W);
    norm_tgt_kernel<<<N_ROWS / 8, 256>>>(x, W, label);

    dim3 grid(STRIPES, N_ROWS / 64);
    gemm_lse_mma<<<grid, 256>>>();

    combine_kernel<<<N_ROWS / 8, 256>>>();
    final_kernel<<<1, 1024>>>(out);
}